// round 14
// baseline (speedup 1.0000x reference)
#include <cuda_runtime.h>
#include <cuda_fp16.h>
#include <math.h>
#include <stdint.h>

#define H 256
#define G3 768
#define FD 128
#define HEADN 128
#define HS_PITCH 36
#define XP 132            // padded SMEM pitch for xgates mma tiles

typedef unsigned long long ull;

__device__ __forceinline__ void cp16(void* smem_dst, const void* gsrc) {
    unsigned d = (unsigned)__cvta_generic_to_shared(smem_dst);
    asm volatile("cp.async.cg.shared.global [%0], [%1], 16;" :: "r"(d), "l"(gsrc));
}
__device__ __forceinline__ void cp4(void* smem_dst, const void* gsrc) {
    unsigned d = (unsigned)__cvta_generic_to_shared(smem_dst);
    asm volatile("cp.async.ca.shared.global [%0], [%1], 4;" :: "r"(d), "l"(gsrc));
}
#define CP_COMMIT asm volatile("cp.async.commit_group;")
#define CP_WAIT2  asm volatile("cp.async.wait_group 2;")
#define CP_WAIT1  asm volatile("cp.async.wait_group 1;")
#define CP_WAIT0  asm volatile("cp.async.wait_group 0;")

__device__ __forceinline__ uint32_t f2tf32(float f) {
    uint32_t o;
    asm("cvt.rna.tf32.f32 %0, %1;" : "=r"(o) : "f"(f));
    return o;
}

// mma.sync m16n8k8 tf32 (A row-major, B col-major), acc in-place
#define MMA_TF32(c, a, b) \
    asm volatile("mma.sync.aligned.m16n8k8.row.col.f32.tf32.tf32.f32 " \
        "{%0,%1,%2,%3}, {%4,%5,%6,%7}, {%8,%9}, {%0,%1,%2,%3};" \
        : "+f"((c)[0]), "+f"((c)[1]), "+f"((c)[2]), "+f"((c)[3]) \
        : "r"((a)[0]), "r"((a)[1]), "r"((a)[2]), "r"((a)[3]), \
          "r"((b)[0]), "r"((b)[1]))

// mma.sync m16n8k16 fp16 (A row-major, B col-major), fp32 acc in-place
#define MMA_F16(c, a, b) \
    asm volatile("mma.sync.aligned.m16n8k16.row.col.f32.f16.f16.f32 " \
        "{%0,%1,%2,%3}, {%4,%5,%6,%7}, {%8,%9}, {%0,%1,%2,%3};" \
        : "+f"((c)[0]), "+f"((c)[1]), "+f"((c)[2]), "+f"((c)[3]) \
        : "r"((a)[0]), "r"((a)[1]), "r"((a)[2]), "r"((a)[3]), \
          "r"((b)[0]), "r"((b)[1]))

__device__ __forceinline__ float sigf(float x) {
    return __fdividef(1.f, 1.f + __expf(-x));
}
__device__ __forceinline__ float tanhfast(float x) {
    return 1.f - __fdividef(2.f, __expf(2.f * x) + 1.f);   // saturation-safe
}

// ---------------- scratch ----------------
__device__ float g_xg[4096UL * 64UL * 768UL];
__device__ float g_whead[H * HEADN];
// w_hh split fp16 hi/lo (hi = rn(w), lo = rn(w - hi); together ~21 bits exact),
// column-reordered n' = (hid/8)*24 + gate*8 + hid%8,
// chunked [16 k16-chunks][2 k8-halves][768 n'][8 fp16]
__device__ __half g_wfhi[16 * 2 * 768 * 8];
__device__ __half g_wflo[16 * 2 * 768 * 8];

// ---------------- kernel 0: pack ----------------
__global__ void pack_weights(const float* __restrict__ w_hh,
                             const float* __restrict__ w_pi,
                             const float* __restrict__ w_vf) {
    int idx = blockIdx.x * blockDim.x + threadIdx.x;
    int stride = gridDim.x * blockDim.x;
    for (int i = idx; i < G3 * H; i += stride) {
        int grow = i >> 8, k = i & 255;
        int gate = grow >> 8, hid = grow & 255;
        int np = (hid >> 3) * 24 + gate * 8 + (hid & 7);
        int c = k >> 4, hf = (k >> 3) & 1, e = k & 7;
        float v = w_hh[grow * H + k];
        __half wh = __float2half_rn(v);
        __half wl = __float2half_rn(v - __half2float(wh));
        size_t d = ((size_t)(c * 2 + hf) * 768 + np) * 8 + e;
        g_wfhi[d] = wh;
        g_wflo[d] = wl;
    }
    for (int i = idx; i < H * HEADN; i += stride) {
        int k = i / HEADN, j = i % HEADN;
        g_whead[i] = (j < 64) ? w_pi[j * H + k] : w_vf[(j - 64) * H + k];
    }
}

// ---------------- kernel 1: x_gates via mma.sync tf32 (unchanged, passing) ----------------
__global__ __launch_bounds__(256, 1) void xgates_mma_sync(const float* __restrict__ feats,
                                                          const float* __restrict__ w_ih,
                                                          const float* __restrict__ b_ih) {
    extern __shared__ uint32_t xs[];
    uint32_t* As = xs;                 // [128][XP]
    uint32_t* Bs = xs + 128 * XP;      // [128][XP]

    const int t = threadIdx.x;
    const int lane = t & 31;
    const int w = t >> 5;
    const int wm = w & 1;
    const int wn = w >> 1;
    const int m0 = blockIdx.x * 128;
    const int n0 = blockIdx.y * 128;

#pragma unroll
    for (int q = 0; q < 16; q++) {
        int idx = t + 256 * q, row = idx >> 5, c4 = idx & 31;
        float4 va = *reinterpret_cast<const float4*>(
            &feats[(size_t)(m0 + row) * FD + c4 * 4]);
        uint4 ua = {f2tf32(va.x), f2tf32(va.y), f2tf32(va.z), f2tf32(va.w)};
        *reinterpret_cast<uint4*>(&As[row * XP + c4 * 4]) = ua;
        float4 vb = *reinterpret_cast<const float4*>(
            &w_ih[(size_t)(n0 + row) * FD + c4 * 4]);
        uint4 ub = {f2tf32(vb.x), f2tf32(vb.y), f2tf32(vb.z), f2tf32(vb.w)};
        *reinterpret_cast<uint4*>(&Bs[row * XP + c4 * 4]) = ub;
    }
    __syncthreads();

    float acc[16][4];
#pragma unroll
    for (int i = 0; i < 16; i++)
#pragma unroll
        for (int j = 0; j < 4; j++) acc[i][j] = 0.f;

    const int rA = wm * 64 + (lane >> 2);
    const int rB = wn * 32 + (lane >> 2);
    const int kl = lane & 3;

#pragma unroll
    for (int ks = 0; ks < 16; ks++) {
        const int k0 = ks * 8 + kl;
        uint32_t a[4][4], b[4][2];
#pragma unroll
        for (int mt = 0; mt < 4; mt++) {
            const int r = rA + mt * 16;
            a[mt][0] = As[r * XP + k0];
            a[mt][1] = As[(r + 8) * XP + k0];
            a[mt][2] = As[r * XP + k0 + 4];
            a[mt][3] = As[(r + 8) * XP + k0 + 4];
        }
#pragma unroll
        for (int nt = 0; nt < 4; nt++) {
            const int n = rB + nt * 8;
            b[nt][0] = Bs[n * XP + k0];
            b[nt][1] = Bs[n * XP + k0 + 4];
        }
#pragma unroll
        for (int mt = 0; mt < 4; mt++)
#pragma unroll
            for (int nt = 0; nt < 4; nt++)
                MMA_TF32(acc[mt * 4 + nt], a[mt], b[nt]);
    }

#pragma unroll
    for (int nt = 0; nt < 4; nt++) {
        const int col = n0 + wn * 32 + nt * 8 + 2 * kl;
        const float bx = b_ih[col], by = b_ih[col + 1];
#pragma unroll
        for (int mt = 0; mt < 4; mt++) {
            const int r = m0 + wm * 64 + mt * 16 + (lane >> 2);
            float2 v0 = {acc[mt * 4 + nt][0] + bx, acc[mt * 4 + nt][1] + by};
            float2 v1 = {acc[mt * 4 + nt][2] + bx, acc[mt * 4 + nt][3] + by};
            *reinterpret_cast<float2*>(&g_xg[(size_t)r * G3 + col]) = v0;
            *reinterpret_cast<float2*>(&g_xg[(size_t)(r + 8) * G3 + col]) = v1;
        }
    }
}

// ---------------- kernel 2: GRU recurrence, fp16 2-pass, barrier-free chunk loop ----
// Thread-private weight slices: each thread cp.asyncs EXACTLY the 192B of each
// 48KB chunk that its own MMA fragments read (4B granules; 128B-coalesced per
// (nt,hf,plane) across the warp). Slice buffer layout [i(48)][thread(256)][4B]
// -> lane-consecutive LDS.32, conflict-free. Visibility = per-thread
// cp.async.wait_group only: NO barriers inside the 16-chunk loop. CTA syncs
// only after A-build and after the gate epilogue (2 per step, was 32+).
#define SM_W0 0
#define SM_W1 49152
#define SM_W2 98304
#define SM_A  147456
#define SM_HS 163840
#define SM_TOT (163840 + 36864)     // 200704 B

__device__ __forceinline__ void load_slice(char* buf, int c, int t,
                                           int wid, int gid, int tig) {
    const char* hi = (const char*)g_wfhi;
    const char* lo = (const char*)g_wflo;
#pragma unroll
    for (int nt = 0; nt < 12; nt++) {
        const int n = wid * 96 + nt * 8 + gid;
#pragma unroll
        for (int hf = 0; hf < 2; hf++) {
            const size_t so = ((size_t)((c * 2 + hf) * 768) + n) * 16 + tig * 4;
            cp4(buf + (nt * 4 + hf) * 1024 + t * 4, hi + so);
            cp4(buf + (nt * 4 + 2 + hf) * 1024 + t * 4, lo + so);
        }
    }
}

__global__ __launch_bounds__(256) void gru_recur(const float* __restrict__ b_hh,
                                                 const float* __restrict__ b_pi,
                                                 const float* __restrict__ b_vf,
                                                 float* __restrict__ out,
                                                 int Btot, int Tsteps) {
    extern __shared__ char smem[];
    float* Hs = reinterpret_cast<float*>(smem + SM_HS);     // [256][36] : Hs[hid][row]
    uint32_t* Au = reinterpret_cast<uint32_t*>(smem + SM_A); // fp16 h plane

    const int t = threadIdx.x;
    const int lane = t & 31;
    const int wid = t >> 5;
    const int gid = lane >> 2;
    const int tig = lane & 3;
    const int b0 = blockIdx.x * 32;

    // hoisted gate biases for this thread's hidden pairs
    float2 bR[4], bZ[4], bN[4];
#pragma unroll
    for (int b = 0; b < 4; b++) {
        const int hid0 = (4 * wid + b) * 8 + tig * 2;
        bR[b] = *reinterpret_cast<const float2*>(&b_hh[hid0]);
        bZ[b] = *reinterpret_cast<const float2*>(&b_hh[H + hid0]);
        bN[b] = *reinterpret_cast<const float2*>(&b_hh[2 * H + hid0]);
    }

    for (int i = t; i < H * HS_PITCH; i += 256) Hs[i] = 0.f;
    __syncthreads();

    for (int st = 0; st < Tsteps; st++) {
        // issue chunk 0 and 1 slice loads (own data only; prior reads precede
        // in program order, so no cross-thread hazard)
        load_slice(smem + SM_W0, 0, t, wid, gid, tig);
        CP_COMMIT;
        load_slice(smem + SM_W1, 1, t, wid, gid, tig);
        CP_COMMIT;

        // A-build: h -> fp16 plane [chunk][k8-half][row][8]
        {
            const int hg = t >> 5;               // hidden group: 32 hids
#pragma unroll
            for (int j = 0; j < 16; j++) {
                const int hid0 = hg * 32 + 2 * j;
                float v0 = Hs[hid0 * HS_PITCH + lane];
                float v1 = Hs[(hid0 + 1) * HS_PITCH + lane];
                __half2 p;
                p.x = __float2half_rn(v0);
                p.y = __float2half_rn(v1);
                const int c = hid0 >> 4, hf = (hid0 >> 3) & 1, e = hid0 & 7;
                const int idx = ((c * 2 + hf) * 32 + lane) * 4 + (e >> 1);
                reinterpret_cast<__half2*>(Au)[idx] = p;
            }
        }
        __syncthreads();                         // A plane visible to all warps

        float acc[2][12][4];
#pragma unroll
        for (int m = 0; m < 2; m++)
#pragma unroll
            for (int nt = 0; nt < 12; nt++)
#pragma unroll
                for (int j = 0; j < 4; j++) acc[m][nt][j] = 0.f;

        char* bA = smem + SM_W0;
        char* bB = smem + SM_W1;
        char* bC = smem + SM_W2;

        for (int c = 0; c < 16; c++) {
            if (c + 2 < 16) {
                load_slice(bC, c + 2, t, wid, gid, tig);
                CP_COMMIT;
                CP_WAIT2;                        // own chunk-c group complete
            } else if (c == 14) {
                CP_WAIT1;
            } else {
                CP_WAIT0;
            }
            const uint32_t* W = reinterpret_cast<const uint32_t*>(bA);
            const uint32_t* Ac = Au + c * 256;

            uint32_t ah[2][4];
#pragma unroll
            for (int m = 0; m < 2; m++) {
                const int base = gid + m * 16;
                ah[m][0] = Ac[base * 4 + tig];
                ah[m][1] = Ac[(base + 8) * 4 + tig];
                ah[m][2] = Ac[128 + base * 4 + tig];
                ah[m][3] = Ac[128 + (base + 8) * 4 + tig];
            }
#pragma unroll
            for (int nt = 0; nt < 12; nt++) {
                uint32_t bh[2], bl[2];
                bh[0] = W[(nt * 4 + 0) * 256 + t];
                bh[1] = W[(nt * 4 + 1) * 256 + t];
                bl[0] = W[(nt * 4 + 2) * 256 + t];
                bl[1] = W[(nt * 4 + 3) * 256 + t];
                MMA_F16(acc[0][nt], ah[0], bh);
                MMA_F16(acc[1][nt], ah[1], bh);
                MMA_F16(acc[0][nt], ah[0], bl);
                MMA_F16(acc[1][nt], ah[1], bl);
            }
            char* tmp = bA; bA = bB; bB = bC; bC = tmp;   // rotate buffers
        }

        // gate epilogue: thread-local r/z/n combine + h update
#pragma unroll
        for (int m = 0; m < 2; m++)
#pragma unroll
            for (int rr = 0; rr < 2; rr++) {
                const int row = gid + m * 16 + rr * 8;
                const size_t gro = ((size_t)(b0 + row) * Tsteps + st) * (size_t)G3;
#pragma unroll
                for (int b = 0; b < 4; b++) {
                    const int hid0 = (4 * wid + b) * 8 + tig * 2;
                    const float2 xr = *reinterpret_cast<const float2*>(&g_xg[gro + hid0]);
                    const float2 xz = *reinterpret_cast<const float2*>(&g_xg[gro + H + hid0]);
                    const float2 xn = *reinterpret_cast<const float2*>(&g_xg[gro + 2 * H + hid0]);
                    const float hr0 = acc[m][b * 3 + 0][rr * 2];
                    const float hr1 = acc[m][b * 3 + 0][rr * 2 + 1];
                    const float hz0 = acc[m][b * 3 + 1][rr * 2];
                    const float hz1 = acc[m][b * 3 + 1][rr * 2 + 1];
                    const float hn0 = acc[m][b * 3 + 2][rr * 2];
                    const float hn1 = acc[m][b * 3 + 2][rr * 2 + 1];
                    {
                        const float r = sigf(xr.x + hr0 + bR[b].x);
                        const float z = sigf(xz.x + hz0 + bZ[b].x);
                        const float n = tanhfast(xn.x + r * (hn0 + bN[b].x));
                        const float hold = Hs[hid0 * HS_PITCH + row];
                        Hs[hid0 * HS_PITCH + row] = (1.f - z) * n + z * hold;
                    }
                    {
                        const float r = sigf(xr.y + hr1 + bR[b].y);
                        const float z = sigf(xz.y + hz1 + bZ[b].y);
                        const float n = tanhfast(xn.y + r * (hn1 + bN[b].y));
                        const float hold = Hs[(hid0 + 1) * HS_PITCH + row];
                        Hs[(hid0 + 1) * HS_PITCH + row] = (1.f - z) * n + z * hold;
                    }
                }
            }
        __syncthreads();                         // Hs complete before next A-build
    }

    // LeakyReLU on final h
    for (int idx = t; idx < H * 32; idx += 256) {
        const int hid = idx >> 5, row = idx & 31;
        float v = Hs[hid * HS_PITCH + row];
        Hs[hid * HS_PITCH + row] = (v >= 0.f) ? v : 0.01f * v;
    }
    __syncthreads();

    // heads: [32,256] @ [256,128] (fp32 scalar, reuse W buffer region)
    float* Ws0 = reinterpret_cast<float*>(smem);
    float acc2[4][4];
#pragma unroll
    for (int i = 0; i < 4; i++)
#pragma unroll
        for (int j = 0; j < 4; j++) acc2[i][j] = 0.f;

    for (int k0 = 0; k0 < H; k0 += 16) {
#pragma unroll
        for (int q = 0; q < 2; q++) {
            int f4 = t + 256 * q, row = f4 >> 5, c4 = f4 & 31;
            *reinterpret_cast<float4*>(&Ws0[row * HEADN + c4 * 4]) =
                *reinterpret_cast<const float4*>(&g_whead[(size_t)(k0 + row) * HEADN + c4 * 4]);
        }
        __syncthreads();
#pragma unroll
        for (int kk = 0; kk < 16; kk++) {
            float4 av = *reinterpret_cast<const float4*>(&Hs[(k0 + kk) * HS_PITCH + wid * 4]);
            float a[4] = {av.x, av.y, av.z, av.w};
#pragma unroll
            for (int j = 0; j < 4; j++) {
                float wt = Ws0[kk * HEADN + lane + 32 * j];
#pragma unroll
                for (int i = 0; i < 4; i++)
                    acc2[i][j] = fmaf(a[i], wt, acc2[i][j]);
            }
        }
        __syncthreads();
    }

#pragma unroll
    for (int j = 0; j < 4; j++) {
        const int c = lane + 32 * j;
        const float bias = (c < 64) ? b_pi[c] : b_vf[c - 64];
#pragma unroll
        for (int ri = 0; ri < 4; ri++) {
            const int row = wid * 4 + ri;
            float y = acc2[ri][j] + bias;
            y = (y >= 0.f) ? y : 0.01f * y;
            size_t o = (c < 64)
                ? ((size_t)(b0 + row) * 64 + c)
                : ((size_t)Btot * 64 + (size_t)(b0 + row) * 64 + (c - 64));
            out[o] = y;
        }
    }
}

// ---------------- launch ----------------
extern "C" void kernel_launch(void* const* d_in, const int* in_sizes, int n_in,
                              void* d_out, int out_size) {
    const float* feats = (const float*)d_in[0];
    const float* w_ih  = (const float*)d_in[1];
    const float* w_hh  = (const float*)d_in[2];
    const float* b_ih  = (const float*)d_in[3];
    const float* b_hh  = (const float*)d_in[4];
    const float* w_pi  = (const float*)d_in[5];
    const float* b_pi  = (const float*)d_in[6];
    const float* w_vf  = (const float*)d_in[7];
    const float* b_vf  = (const float*)d_in[8];
    float* out = (float*)d_out;

    const int Btot   = out_size / 128;
    const int Tsteps = in_sizes[0] / (Btot * FD);
    const int rows   = Btot * Tsteps;

    const size_t smemX = (size_t)(2 * 128 * XP) * sizeof(uint32_t);   // ~132 KB
    cudaFuncSetAttribute(xgates_mma_sync, cudaFuncAttributeMaxDynamicSharedMemorySize, (int)smemX);
    cudaFuncSetAttribute(gru_recur, cudaFuncAttributeMaxDynamicSharedMemorySize, SM_TOT);

    pack_weights<<<64, 256>>>(w_hh, w_pi, w_vf);
    xgates_mma_sync<<<dim3(rows / 128, G3 / 128), 256, smemX>>>(feats, w_ih, b_ih);
    gru_recur<<<Btot / 32, 256, SM_TOT>>>(b_hh, b_pi, b_vf, out, Btot, Tsteps);
}

// round 15
// speedup vs baseline: 1.2577x; 1.2577x over previous
#include <cuda_runtime.h>
#include <cuda_fp16.h>
#include <math.h>
#include <stdint.h>

#define H 256
#define G3 768
#define FD 128
#define HEADN 128
#define HS_PITCH 36
#define XP 132            // padded SMEM pitch for xgates mma tiles

typedef unsigned long long ull;

__device__ __forceinline__ void cp16(void* smem_dst, const void* gsrc) {
    unsigned d = (unsigned)__cvta_generic_to_shared(smem_dst);
    asm volatile("cp.async.cg.shared.global [%0], [%1], 16;" :: "r"(d), "l"(gsrc));
}
#define CP_COMMIT asm volatile("cp.async.commit_group;")
#define CP_WAIT2  asm volatile("cp.async.wait_group 2;")
#define CP_WAIT1  asm volatile("cp.async.wait_group 1;")
#define CP_WAIT0  asm volatile("cp.async.wait_group 0;")

__device__ __forceinline__ uint32_t f2tf32(float f) {
    uint32_t o;
    asm("cvt.rna.tf32.f32 %0, %1;" : "=r"(o) : "f"(f));
    return o;
}

// mma.sync m16n8k8 tf32 (A row-major, B col-major), acc in-place
#define MMA_TF32(c, a, b) \
    asm volatile("mma.sync.aligned.m16n8k8.row.col.f32.tf32.tf32.f32 " \
        "{%0,%1,%2,%3}, {%4,%5,%6,%7}, {%8,%9}, {%0,%1,%2,%3};" \
        : "+f"((c)[0]), "+f"((c)[1]), "+f"((c)[2]), "+f"((c)[3]) \
        : "r"((a)[0]), "r"((a)[1]), "r"((a)[2]), "r"((a)[3]), \
          "r"((b)[0]), "r"((b)[1]))

// mma.sync m16n8k16 fp16 (A row-major, B col-major), fp32 acc in-place
#define MMA_F16(c, a, b) \
    asm volatile("mma.sync.aligned.m16n8k16.row.col.f32.f16.f16.f32 " \
        "{%0,%1,%2,%3}, {%4,%5,%6,%7}, {%8,%9}, {%0,%1,%2,%3};" \
        : "+f"((c)[0]), "+f"((c)[1]), "+f"((c)[2]), "+f"((c)[3]) \
        : "r"((a)[0]), "r"((a)[1]), "r"((a)[2]), "r"((a)[3]), \
          "r"((b)[0]), "r"((b)[1]))

__device__ __forceinline__ float sigf(float x) {
    return __fdividef(1.f, 1.f + __expf(-x));
}
__device__ __forceinline__ float tanhfast(float x) {
    return 1.f - __fdividef(2.f, __expf(2.f * x) + 1.f);   // saturation-safe
}

// ---------------- scratch ----------------
__device__ float g_xg[4096UL * 64UL * 768UL];
__device__ float g_whead[H * HEADN];
// w_hh split fp16 hi/lo (hi = rn(w), lo = rn(w - hi); together ~21 bits exact),
// column-reordered n' = (hid/8)*24 + gate*8 + hid%8,
// chunked [16 k16-chunks][2 k8-halves][768 n'][8 fp16]
__device__ __half g_wfhi[16 * 2 * 768 * 8];
__device__ __half g_wflo[16 * 2 * 768 * 8];

// ---------------- kernel 0: pack ----------------
__global__ void pack_weights(const float* __restrict__ w_hh,
                             const float* __restrict__ w_pi,
                             const float* __restrict__ w_vf) {
    int idx = blockIdx.x * blockDim.x + threadIdx.x;
    int stride = gridDim.x * blockDim.x;
    for (int i = idx; i < G3 * H; i += stride) {
        int grow = i >> 8, k = i & 255;
        int gate = grow >> 8, hid = grow & 255;
        int np = (hid >> 3) * 24 + gate * 8 + (hid & 7);
        int c = k >> 4, hf = (k >> 3) & 1, e = k & 7;
        float v = w_hh[grow * H + k];
        __half wh = __float2half_rn(v);
        __half wl = __float2half_rn(v - __half2float(wh));
        size_t d = ((size_t)(c * 2 + hf) * 768 + np) * 8 + e;
        g_wfhi[d] = wh;
        g_wflo[d] = wl;
    }
    for (int i = idx; i < H * HEADN; i += stride) {
        int k = i / HEADN, j = i % HEADN;
        g_whead[i] = (j < 64) ? w_pi[j * H + k] : w_vf[(j - 64) * H + k];
    }
}

// ---------------- kernel 1: x_gates via mma.sync tf32 (unchanged, passing) ----------------
__global__ __launch_bounds__(256, 1) void xgates_mma_sync(const float* __restrict__ feats,
                                                          const float* __restrict__ w_ih,
                                                          const float* __restrict__ b_ih) {
    extern __shared__ uint32_t xs[];
    uint32_t* As = xs;                 // [128][XP]
    uint32_t* Bs = xs + 128 * XP;      // [128][XP]

    const int t = threadIdx.x;
    const int lane = t & 31;
    const int w = t >> 5;
    const int wm = w & 1;
    const int wn = w >> 1;
    const int m0 = blockIdx.x * 128;
    const int n0 = blockIdx.y * 128;

#pragma unroll
    for (int q = 0; q < 16; q++) {
        int idx = t + 256 * q, row = idx >> 5, c4 = idx & 31;
        float4 va = *reinterpret_cast<const float4*>(
            &feats[(size_t)(m0 + row) * FD + c4 * 4]);
        uint4 ua = {f2tf32(va.x), f2tf32(va.y), f2tf32(va.z), f2tf32(va.w)};
        *reinterpret_cast<uint4*>(&As[row * XP + c4 * 4]) = ua;
        float4 vb = *reinterpret_cast<const float4*>(
            &w_ih[(size_t)(n0 + row) * FD + c4 * 4]);
        uint4 ub = {f2tf32(vb.x), f2tf32(vb.y), f2tf32(vb.z), f2tf32(vb.w)};
        *reinterpret_cast<uint4*>(&Bs[row * XP + c4 * 4]) = ub;
    }
    __syncthreads();

    float acc[16][4];
#pragma unroll
    for (int i = 0; i < 16; i++)
#pragma unroll
        for (int j = 0; j < 4; j++) acc[i][j] = 0.f;

    const int rA = wm * 64 + (lane >> 2);
    const int rB = wn * 32 + (lane >> 2);
    const int kl = lane & 3;

#pragma unroll
    for (int ks = 0; ks < 16; ks++) {
        const int k0 = ks * 8 + kl;
        uint32_t a[4][4], b[4][2];
#pragma unroll
        for (int mt = 0; mt < 4; mt++) {
            const int r = rA + mt * 16;
            a[mt][0] = As[r * XP + k0];
            a[mt][1] = As[(r + 8) * XP + k0];
            a[mt][2] = As[r * XP + k0 + 4];
            a[mt][3] = As[(r + 8) * XP + k0 + 4];
        }
#pragma unroll
        for (int nt = 0; nt < 4; nt++) {
            const int n = rB + nt * 8;
            b[nt][0] = Bs[n * XP + k0];
            b[nt][1] = Bs[n * XP + k0 + 4];
        }
#pragma unroll
        for (int mt = 0; mt < 4; mt++)
#pragma unroll
            for (int nt = 0; nt < 4; nt++)
                MMA_TF32(acc[mt * 4 + nt], a[mt], b[nt]);
    }

#pragma unroll
    for (int nt = 0; nt < 4; nt++) {
        const int col = n0 + wn * 32 + nt * 8 + 2 * kl;
        const float bx = b_ih[col], by = b_ih[col + 1];
#pragma unroll
        for (int mt = 0; mt < 4; mt++) {
            const int r = m0 + wm * 64 + mt * 16 + (lane >> 2);
            float2 v0 = {acc[mt * 4 + nt][0] + bx, acc[mt * 4 + nt][1] + by};
            float2 v1 = {acc[mt * 4 + nt][2] + bx, acc[mt * 4 + nt][3] + by};
            *reinterpret_cast<float2*>(&g_xg[(size_t)r * G3 + col]) = v0;
            *reinterpret_cast<float2*>(&g_xg[(size_t)(r + 8) * G3 + col]) = v1;
        }
    }
}

// ---------------- kernel 2: GRU recurrence, fp16 2-pass, warp-private pipeline ----
// Each warp cp16-loads ONLY its own 6KB of each 48KB chunk (same 12 cp16/thread
// as the cooperative scheme -> zero extra issue cost), so chunk readiness is
// per-warp: cp.async.wait_group + __syncwarp, NO CTA barriers in the chunk loop.
// 4 buffers, 3 chunks in flight. h lives in REGISTERS (hreg); the gate epilogue
// writes the fp16 A-plane directly (A-build phase eliminated). 2 CTA barriers
// per step total (around the epilogue, protecting the shared A-plane).
// Warp slice layout per chunk: [nt(12)][sub(4: hi-hf0,hi-hf1,lo-hf0,lo-hf1)][n8(8)][16B]
#define SM_A   196608                 // fp16 A plane, 16KB (after 4x48KB W buffers)
#define SM_TOT 212992
#define WBUF(i) (smem + (size_t)(i) * 49152)

__device__ __forceinline__ void load_slice(char* buf, int c, int wid, int lane) {
    const char* hi = (const char*)g_wfhi;
    const char* lo = (const char*)g_wflo;
    char* wb = buf + wid * 6144;
#pragma unroll
    for (int q = 0; q < 12; q++) {
        const int g = lane + 32 * q;            // 0..383
        const int n8 = g & 7, sub = (g >> 3) & 3, nt = g >> 5;
        const char* src = (sub & 2) ? lo : hi;
        const int hf = sub & 1;
        const size_t so = ((size_t)((c * 2 + hf) * 768) + wid * 96 + nt * 8 + n8) * 16;
        cp16(wb + g * 16, src + so);
    }
}

__global__ __launch_bounds__(256) void gru_recur(const float* __restrict__ b_hh,
                                                 const float* __restrict__ b_pi,
                                                 const float* __restrict__ b_vf,
                                                 float* __restrict__ out,
                                                 int Btot, int Tsteps) {
    extern __shared__ char smem[];
    uint32_t* Au = reinterpret_cast<uint32_t*>(smem + SM_A);   // fp16 h plane

    const int t = threadIdx.x;
    const int lane = t & 31;
    const int wid = t >> 5;
    const int gid = lane >> 2;
    const int tig = lane & 3;
    const int b0 = blockIdx.x * 32;

    // hoisted gate biases for this thread's hidden pairs
    float2 bR[4], bZ[4], bN[4];
#pragma unroll
    for (int b = 0; b < 4; b++) {
        const int hid0 = (4 * wid + b) * 8 + tig * 2;
        bR[b] = *reinterpret_cast<const float2*>(&b_hh[hid0]);
        bZ[b] = *reinterpret_cast<const float2*>(&b_hh[H + hid0]);
        bN[b] = *reinterpret_cast<const float2*>(&b_hh[2 * H + hid0]);
    }

    // h in registers: hreg[m][rr][b][pair]
    float hreg[2][2][4][2];
#pragma unroll
    for (int m = 0; m < 2; m++)
#pragma unroll
        for (int rr = 0; rr < 2; rr++)
#pragma unroll
            for (int b = 0; b < 4; b++) {
                hreg[m][rr][b][0] = 0.f;
                hreg[m][rr][b][1] = 0.f;
            }

    // zero A plane (h0 = 0)
    for (int i = t; i < 4096; i += 256) Au[i] = 0;
    __syncthreads();

    for (int st = 0; st < Tsteps; st++) {
        // prime pipeline: 3 chunks in flight (warp-private slices)
        load_slice(WBUF(0), 0, wid, lane); CP_COMMIT;
        load_slice(WBUF(1), 1, wid, lane); CP_COMMIT;
        load_slice(WBUF(2), 2, wid, lane); CP_COMMIT;

        float acc[2][12][4];
#pragma unroll
        for (int m = 0; m < 2; m++)
#pragma unroll
            for (int nt = 0; nt < 12; nt++)
#pragma unroll
                for (int j = 0; j < 4; j++) acc[m][nt][j] = 0.f;

        for (int c = 0; c < 16; c++) {
            if (c <= 13)      { CP_WAIT2; }      // completes this warp's chunk c
            else if (c == 14) { CP_WAIT1; }
            else              { CP_WAIT0; }
            __syncwarp();                        // intra-warp visibility
            if (c + 3 < 16) {
                load_slice(WBUF((c + 3) & 3), c + 3, wid, lane);
                CP_COMMIT;
            }
            const uint32_t* Wb = reinterpret_cast<const uint32_t*>(
                WBUF(c & 3) + wid * 6144);
            const uint32_t* Ac = Au + c * 256;

            uint32_t ah[2][4];
#pragma unroll
            for (int m = 0; m < 2; m++) {
                const int base = gid + m * 16;
                ah[m][0] = Ac[base * 4 + tig];
                ah[m][1] = Ac[(base + 8) * 4 + tig];
                ah[m][2] = Ac[128 + base * 4 + tig];
                ah[m][3] = Ac[128 + (base + 8) * 4 + tig];
            }
#pragma unroll
            for (int nt = 0; nt < 12; nt++) {
                uint32_t bh[2], bl[2];
                bh[0] = Wb[((nt * 4 + 0) * 8 + gid) * 4 + tig];
                bh[1] = Wb[((nt * 4 + 1) * 8 + gid) * 4 + tig];
                bl[0] = Wb[((nt * 4 + 2) * 8 + gid) * 4 + tig];
                bl[1] = Wb[((nt * 4 + 3) * 8 + gid) * 4 + tig];
                MMA_F16(acc[0][nt], ah[0], bh);
                MMA_F16(acc[1][nt], ah[1], bh);
                MMA_F16(acc[0][nt], ah[0], bl);
                MMA_F16(acc[1][nt], ah[1], bl);
            }
        }
        __syncthreads();                         // all A-plane reads complete

        // gate epilogue: thread-local combine, hreg update, direct A-plane write
        __half2* Ah2 = reinterpret_cast<__half2*>(Au);
#pragma unroll
        for (int m = 0; m < 2; m++)
#pragma unroll
            for (int rr = 0; rr < 2; rr++) {
                const int row = gid + m * 16 + rr * 8;
                const size_t gro = ((size_t)(b0 + row) * Tsteps + st) * (size_t)G3;
#pragma unroll
                for (int b = 0; b < 4; b++) {
                    const int hid0 = (4 * wid + b) * 8 + tig * 2;
                    const float2 xr = *reinterpret_cast<const float2*>(&g_xg[gro + hid0]);
                    const float2 xz = *reinterpret_cast<const float2*>(&g_xg[gro + H + hid0]);
                    const float2 xn = *reinterpret_cast<const float2*>(&g_xg[gro + 2 * H + hid0]);
                    const float hr0 = acc[m][b * 3 + 0][rr * 2];
                    const float hr1 = acc[m][b * 3 + 0][rr * 2 + 1];
                    const float hz0 = acc[m][b * 3 + 1][rr * 2];
                    const float hz1 = acc[m][b * 3 + 1][rr * 2 + 1];
                    const float hn0 = acc[m][b * 3 + 2][rr * 2];
                    const float hn1 = acc[m][b * 3 + 2][rr * 2 + 1];
                    float h0, h1;
                    {
                        const float r = sigf(xr.x + hr0 + bR[b].x);
                        const float z = sigf(xz.x + hz0 + bZ[b].x);
                        const float n = tanhfast(xn.x + r * (hn0 + bN[b].x));
                        h0 = (1.f - z) * n + z * hreg[m][rr][b][0];
                    }
                    {
                        const float r = sigf(xr.y + hr1 + bR[b].y);
                        const float z = sigf(xz.y + hz1 + bZ[b].y);
                        const float n = tanhfast(xn.y + r * (hn1 + bN[b].y));
                        h1 = (1.f - z) * n + z * hreg[m][rr][b][1];
                    }
                    hreg[m][rr][b][0] = h0;
                    hreg[m][rr][b][1] = h1;
                    __half2 p;
                    p.x = __float2half_rn(h0);
                    p.y = __float2half_rn(h1);
                    Ah2[((4 * wid + b) * 32 + row) * 4 + tig] = p;
                }
            }
        __syncthreads();                         // A-plane visible for next step
    }

    // stage final h (LeakyReLU) into SMEM for the heads GEMM
    float* Hs = reinterpret_cast<float*>(smem);              // [256][36]
#pragma unroll
    for (int m = 0; m < 2; m++)
#pragma unroll
        for (int rr = 0; rr < 2; rr++) {
            const int row = gid + m * 16 + rr * 8;
#pragma unroll
            for (int b = 0; b < 4; b++) {
                const int hid0 = (4 * wid + b) * 8 + tig * 2;
                float v0 = hreg[m][rr][b][0];
                float v1 = hreg[m][rr][b][1];
                v0 = (v0 >= 0.f) ? v0 : 0.01f * v0;
                v1 = (v1 >= 0.f) ? v1 : 0.01f * v1;
                Hs[hid0 * HS_PITCH + row] = v0;
                Hs[(hid0 + 1) * HS_PITCH + row] = v1;
            }
        }
    __syncthreads();

    // heads: [32,256] @ [256,128] (fp32 scalar; weights staged past Hs region)
    float* Ws0 = reinterpret_cast<float*>(smem + 49152);
    float acc2[4][4];
#pragma unroll
    for (int i = 0; i < 4; i++)
#pragma unroll
        for (int j = 0; j < 4; j++) acc2[i][j] = 0.f;

    for (int k0 = 0; k0 < H; k0 += 16) {
#pragma unroll
        for (int q = 0; q < 2; q++) {
            int f4 = t + 256 * q, row = f4 >> 5, c4 = f4 & 31;
            *reinterpret_cast<float4*>(&Ws0[row * HEADN + c4 * 4]) =
                *reinterpret_cast<const float4*>(&g_whead[(size_t)(k0 + row) * HEADN + c4 * 4]);
        }
        __syncthreads();
#pragma unroll
        for (int kk = 0; kk < 16; kk++) {
            float4 av = *reinterpret_cast<const float4*>(&Hs[(k0 + kk) * HS_PITCH + wid * 4]);
            float a[4] = {av.x, av.y, av.z, av.w};
#pragma unroll
            for (int j = 0; j < 4; j++) {
                float wt = Ws0[kk * HEADN + lane + 32 * j];
#pragma unroll
                for (int i = 0; i < 4; i++)
                    acc2[i][j] = fmaf(a[i], wt, acc2[i][j]);
            }
        }
        __syncthreads();
    }

#pragma unroll
    for (int j = 0; j < 4; j++) {
        const int c = lane + 32 * j;
        const float bias = (c < 64) ? b_pi[c] : b_vf[c - 64];
#pragma unroll
        for (int ri = 0; ri < 4; ri++) {
            const int row = wid * 4 + ri;
            float y = acc2[ri][j] + bias;
            y = (y >= 0.f) ? y : 0.01f * y;
            size_t o = (c < 64)
                ? ((size_t)(b0 + row) * 64 + c)
                : ((size_t)Btot * 64 + (size_t)(b0 + row) * 64 + (c - 64));
            out[o] = y;
        }
    }
}

// ---------------- launch ----------------
extern "C" void kernel_launch(void* const* d_in, const int* in_sizes, int n_in,
                              void* d_out, int out_size) {
    const float* feats = (const float*)d_in[0];
    const float* w_ih  = (const float*)d_in[1];
    const float* w_hh  = (const float*)d_in[2];
    const float* b_ih  = (const float*)d_in[3];
    const float* b_hh  = (const float*)d_in[4];
    const float* w_pi  = (const float*)d_in[5];
    const float* b_pi  = (const float*)d_in[6];
    const float* w_vf  = (const float*)d_in[7];
    const float* b_vf  = (const float*)d_in[8];
    float* out = (float*)d_out;

    const int Btot   = out_size / 128;
    const int Tsteps = in_sizes[0] / (Btot * FD);
    const int rows   = Btot * Tsteps;

    const size_t smemX = (size_t)(2 * 128 * XP) * sizeof(uint32_t);   // ~132 KB
    cudaFuncSetAttribute(xgates_mma_sync, cudaFuncAttributeMaxDynamicSharedMemorySize, (int)smemX);
    cudaFuncSetAttribute(gru_recur, cudaFuncAttributeMaxDynamicSharedMemorySize, SM_TOT);

    pack_weights<<<64, 256>>>(w_hh, w_pi, w_vf);
    xgates_mma_sync<<<dim3(rows / 128, G3 / 128), 256, smemX>>>(feats, w_ih, b_ih);
    gru_recur<<<Btot / 32, 256, SM_TOT>>>(b_hh, b_pi, b_vf, out, Btot, Tsteps);
}

// round 16
// speedup vs baseline: 1.5509x; 1.2332x over previous
#include <cuda_runtime.h>
#include <cuda_fp16.h>
#include <math.h>
#include <stdint.h>

#define H 256
#define G3 768
#define FD 128
#define HEADN 128
#define HS_PITCH 36
#define XP 132            // padded SMEM pitch for xgates mma tiles

typedef unsigned long long ull;

__device__ __forceinline__ void cp16(void* smem_dst, const void* gsrc) {
    unsigned d = (unsigned)__cvta_generic_to_shared(smem_dst);
    asm volatile("cp.async.cg.shared.global [%0], [%1], 16;" :: "r"(d), "l"(gsrc));
}
#define CP_COMMIT asm volatile("cp.async.commit_group;")
#define CP_WAIT2  asm volatile("cp.async.wait_group 2;")
#define CP_WAIT1  asm volatile("cp.async.wait_group 1;")
#define CP_WAIT0  asm volatile("cp.async.wait_group 0;")

__device__ __forceinline__ uint32_t f2tf32(float f) {
    uint32_t o;
    asm("cvt.rna.tf32.f32 %0, %1;" : "=r"(o) : "f"(f));
    return o;
}

// mma.sync m16n8k8 tf32 (A row-major, B col-major), acc in-place
#define MMA_TF32(c, a, b) \
    asm volatile("mma.sync.aligned.m16n8k8.row.col.f32.tf32.tf32.f32 " \
        "{%0,%1,%2,%3}, {%4,%5,%6,%7}, {%8,%9}, {%0,%1,%2,%3};" \
        : "+f"((c)[0]), "+f"((c)[1]), "+f"((c)[2]), "+f"((c)[3]) \
        : "r"((a)[0]), "r"((a)[1]), "r"((a)[2]), "r"((a)[3]), \
          "r"((b)[0]), "r"((b)[1]))

// mma.sync m16n8k16 fp16 (A row-major, B col-major), fp32 acc in-place
#define MMA_F16(c, a, b) \
    asm volatile("mma.sync.aligned.m16n8k16.row.col.f32.f16.f16.f32 " \
        "{%0,%1,%2,%3}, {%4,%5,%6,%7}, {%8,%9}, {%0,%1,%2,%3};" \
        : "+f"((c)[0]), "+f"((c)[1]), "+f"((c)[2]), "+f"((c)[3]) \
        : "r"((a)[0]), "r"((a)[1]), "r"((a)[2]), "r"((a)[3]), \
          "r"((b)[0]), "r"((b)[1]))

__device__ __forceinline__ float sigf(float x) {
    return __fdividef(1.f, 1.f + __expf(-x));
}
__device__ __forceinline__ float tanhfast(float x) {
    return 1.f - __fdividef(2.f, __expf(2.f * x) + 1.f);   // saturation-safe
}

// ---------------- scratch ----------------
__device__ float g_xg[4096UL * 64UL * 768UL];
__device__ float g_whead[H * HEADN];
// w_hh in fp16 (single plane; rn(w) — |w|<=1/16 so quantization <= 2^-11 rel),
// column-reordered n' = (hid/8)*24 + gate*8 + hid%8,
// chunked [16 k16-chunks][2 k8-halves][768 n'][8 fp16]
__device__ __half g_wfhi[16 * 2 * 768 * 8];

// ---------------- kernel 0: pack ----------------
__global__ void pack_weights(const float* __restrict__ w_hh,
                             const float* __restrict__ w_pi,
                             const float* __restrict__ w_vf) {
    int idx = blockIdx.x * blockDim.x + threadIdx.x;
    int stride = gridDim.x * blockDim.x;
    for (int i = idx; i < G3 * H; i += stride) {
        int grow = i >> 8, k = i & 255;
        int gate = grow >> 8, hid = grow & 255;
        int np = (hid >> 3) * 24 + gate * 8 + (hid & 7);
        int c = k >> 4, hf = (k >> 3) & 1, e = k & 7;
        float v = w_hh[grow * H + k];
        size_t d = ((size_t)(c * 2 + hf) * 768 + np) * 8 + e;
        g_wfhi[d] = __float2half_rn(v);
    }
    for (int i = idx; i < H * HEADN; i += stride) {
        int k = i / HEADN, j = i % HEADN;
        g_whead[i] = (j < 64) ? w_pi[j * H + k] : w_vf[(j - 64) * H + k];
    }
}

// ---------------- kernel 1: x_gates via mma.sync tf32 (unchanged, passing) ----------------
__global__ __launch_bounds__(256, 1) void xgates_mma_sync(const float* __restrict__ feats,
                                                          const float* __restrict__ w_ih,
                                                          const float* __restrict__ b_ih) {
    extern __shared__ uint32_t xs[];
    uint32_t* As = xs;                 // [128][XP]
    uint32_t* Bs = xs + 128 * XP;      // [128][XP]

    const int t = threadIdx.x;
    const int lane = t & 31;
    const int w = t >> 5;
    const int wm = w & 1;
    const int wn = w >> 1;
    const int m0 = blockIdx.x * 128;
    const int n0 = blockIdx.y * 128;

#pragma unroll
    for (int q = 0; q < 16; q++) {
        int idx = t + 256 * q, row = idx >> 5, c4 = idx & 31;
        float4 va = *reinterpret_cast<const float4*>(
            &feats[(size_t)(m0 + row) * FD + c4 * 4]);
        uint4 ua = {f2tf32(va.x), f2tf32(va.y), f2tf32(va.z), f2tf32(va.w)};
        *reinterpret_cast<uint4*>(&As[row * XP + c4 * 4]) = ua;
        float4 vb = *reinterpret_cast<const float4*>(
            &w_ih[(size_t)(n0 + row) * FD + c4 * 4]);
        uint4 ub = {f2tf32(vb.x), f2tf32(vb.y), f2tf32(vb.z), f2tf32(vb.w)};
        *reinterpret_cast<uint4*>(&Bs[row * XP + c4 * 4]) = ub;
    }
    __syncthreads();

    float acc[16][4];
#pragma unroll
    for (int i = 0; i < 16; i++)
#pragma unroll
        for (int j = 0; j < 4; j++) acc[i][j] = 0.f;

    const int rA = wm * 64 + (lane >> 2);
    const int rB = wn * 32 + (lane >> 2);
    const int kl = lane & 3;

#pragma unroll
    for (int ks = 0; ks < 16; ks++) {
        const int k0 = ks * 8 + kl;
        uint32_t a[4][4], b[4][2];
#pragma unroll
        for (int mt = 0; mt < 4; mt++) {
            const int r = rA + mt * 16;
            a[mt][0] = As[r * XP + k0];
            a[mt][1] = As[(r + 8) * XP + k0];
            a[mt][2] = As[r * XP + k0 + 4];
            a[mt][3] = As[(r + 8) * XP + k0 + 4];
        }
#pragma unroll
        for (int nt = 0; nt < 4; nt++) {
            const int n = rB + nt * 8;
            b[nt][0] = Bs[n * XP + k0];
            b[nt][1] = Bs[n * XP + k0 + 4];
        }
#pragma unroll
        for (int mt = 0; mt < 4; mt++)
#pragma unroll
            for (int nt = 0; nt < 4; nt++)
                MMA_TF32(acc[mt * 4 + nt], a[mt], b[nt]);
    }

#pragma unroll
    for (int nt = 0; nt < 4; nt++) {
        const int col = n0 + wn * 32 + nt * 8 + 2 * kl;
        const float bx = b_ih[col], by = b_ih[col + 1];
#pragma unroll
        for (int mt = 0; mt < 4; mt++) {
            const int r = m0 + wm * 64 + mt * 16 + (lane >> 2);
            float2 v0 = {acc[mt * 4 + nt][0] + bx, acc[mt * 4 + nt][1] + by};
            float2 v1 = {acc[mt * 4 + nt][2] + bx, acc[mt * 4 + nt][3] + by};
            *reinterpret_cast<float2*>(&g_xg[(size_t)r * G3 + col]) = v0;
            *reinterpret_cast<float2*>(&g_xg[(size_t)(r + 8) * G3 + col]) = v1;
        }
    }
}

// ---------------- kernel 2: GRU recurrence, fp16 SINGLE-pass, warp-private pipeline ----
// vs R15: the lo weight plane is dropped (w quantization 2^-11 rel; recurrent
// accumulation of the resulting noise stays ~2e-4, see round theory). MMAs per
// warp per chunk: 48 -> 24; weight slice per warp per chunk: 6KB -> 3KB
// (6 cp16/thread). Pipeline/register-h/epilogue identical to the passing R15.
// Warp slice layout per chunk: [nt(12)][hf(2)][n8(8)][16B]
#define SM_A   98304                  // fp16 A plane, 16KB (after 4x24KB W buffers)
#define SM_TOT 114688
#define WBUF(i) (smem + (size_t)(i) * 24576)

__device__ __forceinline__ void load_slice(char* buf, int c, int wid, int lane) {
    const char* hi = (const char*)g_wfhi;
    char* wb = buf + wid * 3072;
#pragma unroll
    for (int q = 0; q < 6; q++) {
        const int g = lane + 32 * q;            // 0..191
        const int n8 = g & 7, hf = (g >> 3) & 1, nt = g >> 4;
        const size_t so = ((size_t)((c * 2 + hf) * 768) + wid * 96 + nt * 8 + n8) * 16;
        cp16(wb + g * 16, hi + so);
    }
}

__global__ __launch_bounds__(256) void gru_recur(const float* __restrict__ b_hh,
                                                 const float* __restrict__ b_pi,
                                                 const float* __restrict__ b_vf,
                                                 float* __restrict__ out,
                                                 int Btot, int Tsteps) {
    extern __shared__ char smem[];
    uint32_t* Au = reinterpret_cast<uint32_t*>(smem + SM_A);   // fp16 h plane

    const int t = threadIdx.x;
    const int lane = t & 31;
    const int wid = t >> 5;
    const int gid = lane >> 2;
    const int tig = lane & 3;
    const int b0 = blockIdx.x * 32;

    // hoisted gate biases for this thread's hidden pairs
    float2 bR[4], bZ[4], bN[4];
#pragma unroll
    for (int b = 0; b < 4; b++) {
        const int hid0 = (4 * wid + b) * 8 + tig * 2;
        bR[b] = *reinterpret_cast<const float2*>(&b_hh[hid0]);
        bZ[b] = *reinterpret_cast<const float2*>(&b_hh[H + hid0]);
        bN[b] = *reinterpret_cast<const float2*>(&b_hh[2 * H + hid0]);
    }

    // h in registers: hreg[m][rr][b][pair]
    float hreg[2][2][4][2];
#pragma unroll
    for (int m = 0; m < 2; m++)
#pragma unroll
        for (int rr = 0; rr < 2; rr++)
#pragma unroll
            for (int b = 0; b < 4; b++) {
                hreg[m][rr][b][0] = 0.f;
                hreg[m][rr][b][1] = 0.f;
            }

    // zero A plane (h0 = 0)
    for (int i = t; i < 4096; i += 256) Au[i] = 0;
    __syncthreads();

    for (int st = 0; st < Tsteps; st++) {
        // prime pipeline: 3 chunks in flight (warp-private slices)
        load_slice(WBUF(0), 0, wid, lane); CP_COMMIT;
        load_slice(WBUF(1), 1, wid, lane); CP_COMMIT;
        load_slice(WBUF(2), 2, wid, lane); CP_COMMIT;

        float acc[2][12][4];
#pragma unroll
        for (int m = 0; m < 2; m++)
#pragma unroll
            for (int nt = 0; nt < 12; nt++)
#pragma unroll
                for (int j = 0; j < 4; j++) acc[m][nt][j] = 0.f;

        for (int c = 0; c < 16; c++) {
            if (c <= 13)      { CP_WAIT2; }      // completes this warp's chunk c
            else if (c == 14) { CP_WAIT1; }
            else              { CP_WAIT0; }
            __syncwarp();                        // intra-warp visibility
            if (c + 3 < 16) {
                load_slice(WBUF((c + 3) & 3), c + 3, wid, lane);
                CP_COMMIT;
            }
            const uint32_t* Wb = reinterpret_cast<const uint32_t*>(
                WBUF(c & 3) + wid * 3072);
            const uint32_t* Ac = Au + c * 256;

            uint32_t ah[2][4];
#pragma unroll
            for (int m = 0; m < 2; m++) {
                const int base = gid + m * 16;
                ah[m][0] = Ac[base * 4 + tig];
                ah[m][1] = Ac[(base + 8) * 4 + tig];
                ah[m][2] = Ac[128 + base * 4 + tig];
                ah[m][3] = Ac[128 + (base + 8) * 4 + tig];
            }
#pragma unroll
            for (int nt = 0; nt < 12; nt++) {
                uint32_t bh[2];
                bh[0] = Wb[((nt * 2 + 0) * 8 + gid) * 4 + tig];
                bh[1] = Wb[((nt * 2 + 1) * 8 + gid) * 4 + tig];
                MMA_F16(acc[0][nt], ah[0], bh);
                MMA_F16(acc[1][nt], ah[1], bh);
            }
        }
        __syncthreads();                         // all A-plane reads complete

        // gate epilogue: thread-local combine, hreg update, direct A-plane write
        __half2* Ah2 = reinterpret_cast<__half2*>(Au);
#pragma unroll
        for (int m = 0; m < 2; m++)
#pragma unroll
            for (int rr = 0; rr < 2; rr++) {
                const int row = gid + m * 16 + rr * 8;
                const size_t gro = ((size_t)(b0 + row) * Tsteps + st) * (size_t)G3;
#pragma unroll
                for (int b = 0; b < 4; b++) {
                    const int hid0 = (4 * wid + b) * 8 + tig * 2;
                    const float2 xr = *reinterpret_cast<const float2*>(&g_xg[gro + hid0]);
                    const float2 xz = *reinterpret_cast<const float2*>(&g_xg[gro + H + hid0]);
                    const float2 xn = *reinterpret_cast<const float2*>(&g_xg[gro + 2 * H + hid0]);
                    const float hr0 = acc[m][b * 3 + 0][rr * 2];
                    const float hr1 = acc[m][b * 3 + 0][rr * 2 + 1];
                    const float hz0 = acc[m][b * 3 + 1][rr * 2];
                    const float hz1 = acc[m][b * 3 + 1][rr * 2 + 1];
                    const float hn0 = acc[m][b * 3 + 2][rr * 2];
                    const float hn1 = acc[m][b * 3 + 2][rr * 2 + 1];
                    float h0, h1;
                    {
                        const float r = sigf(xr.x + hr0 + bR[b].x);
                        const float z = sigf(xz.x + hz0 + bZ[b].x);
                        const float n = tanhfast(xn.x + r * (hn0 + bN[b].x));
                        h0 = (1.f - z) * n + z * hreg[m][rr][b][0];
                    }
                    {
                        const float r = sigf(xr.y + hr1 + bR[b].y);
                        const float z = sigf(xz.y + hz1 + bZ[b].y);
                        const float n = tanhfast(xn.y + r * (hn1 + bN[b].y));
                        h1 = (1.f - z) * n + z * hreg[m][rr][b][1];
                    }
                    hreg[m][rr][b][0] = h0;
                    hreg[m][rr][b][1] = h1;
                    __half2 p;
                    p.x = __float2half_rn(h0);
                    p.y = __float2half_rn(h1);
                    Ah2[((4 * wid + b) * 32 + row) * 4 + tig] = p;
                }
            }
        __syncthreads();                         // A-plane visible for next step
    }

    // stage final h (LeakyReLU) into SMEM for the heads GEMM
    float* Hs = reinterpret_cast<float*>(smem);              // [256][36]
#pragma unroll
    for (int m = 0; m < 2; m++)
#pragma unroll
        for (int rr = 0; rr < 2; rr++) {
            const int row = gid + m * 16 + rr * 8;
#pragma unroll
            for (int b = 0; b < 4; b++) {
                const int hid0 = (4 * wid + b) * 8 + tig * 2;
                float v0 = hreg[m][rr][b][0];
                float v1 = hreg[m][rr][b][1];
                v0 = (v0 >= 0.f) ? v0 : 0.01f * v0;
                v1 = (v1 >= 0.f) ? v1 : 0.01f * v1;
                Hs[hid0 * HS_PITCH + row] = v0;
                Hs[(hid0 + 1) * HS_PITCH + row] = v1;
            }
        }
    __syncthreads();

    // heads: [32,256] @ [256,128] (fp32 scalar; weights staged past Hs region)
    float* Ws0 = reinterpret_cast<float*>(smem + 49152);
    float acc2[4][4];
#pragma unroll
    for (int i = 0; i < 4; i++)
#pragma unroll
        for (int j = 0; j < 4; j++) acc2[i][j] = 0.f;

    for (int k0 = 0; k0 < H; k0 += 16) {
#pragma unroll
        for (int q = 0; q < 2; q++) {
            int f4 = t + 256 * q, row = f4 >> 5, c4 = f4 & 31;
            *reinterpret_cast<float4*>(&Ws0[row * HEADN + c4 * 4]) =
                *reinterpret_cast<const float4*>(&g_whead[(size_t)(k0 + row) * HEADN + c4 * 4]);
        }
        __syncthreads();
#pragma unroll
        for (int kk = 0; kk < 16; kk++) {
            float4 av = *reinterpret_cast<const float4*>(&Hs[(k0 + kk) * HS_PITCH + wid * 4]);
            float a[4] = {av.x, av.y, av.z, av.w};
#pragma unroll
            for (int j = 0; j < 4; j++) {
                float wt = Ws0[kk * HEADN + lane + 32 * j];
#pragma unroll
                for (int i = 0; i < 4; i++)
                    acc2[i][j] = fmaf(a[i], wt, acc2[i][j]);
            }
        }
        __syncthreads();
    }

#pragma unroll
    for (int j = 0; j < 4; j++) {
        const int c = lane + 32 * j;
        const float bias = (c < 64) ? b_pi[c] : b_vf[c - 64];
#pragma unroll
        for (int ri = 0; ri < 4; ri++) {
            const int row = wid * 4 + ri;
            float y = acc2[ri][j] + bias;
            y = (y >= 0.f) ? y : 0.01f * y;
            size_t o = (c < 64)
                ? ((size_t)(b0 + row) * 64 + c)
                : ((size_t)Btot * 64 + (size_t)(b0 + row) * 64 + (c - 64));
            out[o] = y;
        }
    }
}

// ---------------- launch ----------------
extern "C" void kernel_launch(void* const* d_in, const int* in_sizes, int n_in,
                              void* d_out, int out_size) {
    const float* feats = (const float*)d_in[0];
    const float* w_ih  = (const float*)d_in[1];
    const float* w_hh  = (const float*)d_in[2];
    const float* b_ih  = (const float*)d_in[3];
    const float* b_hh  = (const float*)d_in[4];
    const float* w_pi  = (const float*)d_in[5];
    const float* b_pi  = (const float*)d_in[6];
    const float* w_vf  = (const float*)d_in[7];
    const float* b_vf  = (const float*)d_in[8];
    float* out = (float*)d_out;

    const int Btot   = out_size / 128;
    const int Tsteps = in_sizes[0] / (Btot * FD);
    const int rows   = Btot * Tsteps;

    const size_t smemX = (size_t)(2 * 128 * XP) * sizeof(uint32_t);   // ~132 KB
    cudaFuncSetAttribute(xgates_mma_sync, cudaFuncAttributeMaxDynamicSharedMemorySize, (int)smemX);
    cudaFuncSetAttribute(gru_recur, cudaFuncAttributeMaxDynamicSharedMemorySize, SM_TOT);

    pack_weights<<<64, 256>>>(w_hh, w_pi, w_vf);
    xgates_mma_sync<<<dim3(rows / 128, G3 / 128), 256, smemX>>>(feats, w_ih, b_ih);
    gru_recur<<<Btot / 32, 256, SM_TOT>>>(b_hh, b_pi, b_vf, out, Btot, Tsteps);
}